// round 8
// baseline (speedup 1.0000x reference)
#include <cuda_runtime.h>

// MorphologicalDegradation, i=30 fixed: k=7 circular SE, dilation, weight=0.24.
//   out = clip(0.76*x + 0.24*(1 - prod_taps(1 - x_shift)), 0, 1)
// Row decomposition (half-widths by dy): {0,2,2,3,2,2,0}:
//   out(y) = f( t(y-3) * h2(y-2) * h2(y-1) * h3(y) * h2(y+1) * h2(y+2) * t(y+3) )
//
// R8 (base = R7 shuffle-halo): stall-directed changes.
//  (1) center-row prefetch depth 2 -> 3 (~270cyc lookahead >= L2 hit lat 234-262)
//  (2) ROUT 7 -> 4: 8192 warps / 1024 blocks (~1.7 waves) to fill latency holes
//      and amortize CTA-spread tail (R7 was a single exact wave, occ 39%).
//  (3) __stcs streaming stores (output never re-read; protect L2-resident input)
//      + __ldg on reads.

static constexpr int Hh     = 512;
static constexpr int Ww     = 512;
static constexpr int ROUT   = 4;             // output rows per warp-chunk
static constexpr int CHUNKS = 128;           // 512/4
static constexpr int ITERS  = ROUT + 6;      // 10 input rows streamed

__device__ __forceinline__ float4 zero4() { return make_float4(0.f, 0.f, 0.f, 0.f); }

__global__ void __launch_bounds__(256, 4)
morph_kernel(const float* __restrict__ x, float* __restrict__ out)
{
    const int gt    = blockIdx.x * 256 + threadIdx.x;
    const int gw    = gt >> 5;            // global warp id, 0..8191
    const int ln    = gt & 31;
    const int wp    = gw & 3;             // column quadrant (128 cols each)
    const int gwq   = gw >> 2;            // 0..2047
    const int chunk = gwq & (CHUNKS - 1); // row chunk
    const int img   = gwq >> 7;           // 16 images

    const int c0 = wp * 128 + ln * 4;     // first of 4 owned columns
    const int y0 = chunk * ROUT;

    const float* base  = x   + img * (Hh * Ww);
    float*       obase = out + img * (Hh * Ww);

    const float WGT  = 0.24f;
    const float IWGT = 1.0f - 0.24f;

    const bool laneL = (ln == 0)  && (c0 >= 4);          // left warp-boundary load
    const bool laneR = (ln == 31) && (c0 + 4 <= Ww - 4); // right warp-boundary load

    float4 acc[7];   // rotating accumulators (4 columns each)

    auto loadM = [&](int ii) -> float4 {
        const int r = y0 - 3 + ii;
        return ((unsigned)r < (unsigned)Hh)
            ? __ldg((const float4*)(base + r * Ww + c0)) : zero4();
    };

    // center-row pipeline, depth 3
    float4 M0 = loadM(0);
    float4 M1 = loadM(1);
    float4 M2 = loadM(2);

#pragma unroll
    for (int ii = 0; ii < ITERS; ++ii) {
        const int r = y0 - 3 + ii;

        // prefetch center row at depth 3
        float4 Mnew = (ii + 3 < ITERS) ? loadM(ii + 3) : zero4();

        // warp-boundary halos: 1-lane predicated loads (current row)
        float4 Lh = zero4(), Rh = zero4();
        if (laneL && (unsigned)r < (unsigned)Hh) Lh = __ldg((const float4*)(base + r * Ww + c0 - 4));
        if (laneR && (unsigned)r < (unsigned)Hh) Rh = __ldg((const float4*)(base + r * Ww + c0 + 4));

        // reload raw x for the emit row early (L1 hit; loaded 3 iters ago).
        // y = y0+ii-6 in [y0, y0+3] subset [0,511] -> no bounds check needed.
        const int y = y0 + ii - 6;
        const bool emit = (ii >= 6);
        float4 xv;
        if (emit) xv = __ldg((const float4*)(base + y * Ww + c0));

        // own t-values (cols c0..c0+3)
        const float tm0 = 1.f - M0.x, tm1 = 1.f - M0.y, tm2 = 1.f - M0.z, tm3 = 1.f - M0.w;

        // halo t-values from neighbor lanes (lane-1 owns c0-4.., lane+1 owns c0+4..)
        float t1 = __shfl_up_sync(0xffffffffu, tm1, 1);   // t(c0-3)
        float t2 = __shfl_up_sync(0xffffffffu, tm2, 1);   // t(c0-2)
        float t3 = __shfl_up_sync(0xffffffffu, tm3, 1);   // t(c0-1)
        float t8 = __shfl_down_sync(0xffffffffu, tm0, 1); // t(c0+4)
        float t9 = __shfl_down_sync(0xffffffffu, tm1, 1); // t(c0+5)
        float t10= __shfl_down_sync(0xffffffffu, tm2, 1); // t(c0+6)
        if (ln == 0)  { t1 = 1.f - Lh.y; t2 = 1.f - Lh.z; t3 = 1.f - Lh.w; }
        if (ln == 31) { t8 = 1.f - Rh.x; t9 = 1.f - Rh.y; t10 = 1.f - Rh.z; }
        // (image-edge lanes: Lh/Rh stay zero -> t = 1, matching zero-pad)

        const float t4 = tm0, t5 = tm1, t6 = tm2, t7 = tm3;

        float h2[4], h3[4];
        { float p = t2 * t3; p *= t4; p *= t5; p *= t6; h2[0] = p; }
        { float p = t3 * t4; p *= t5; p *= t6; p *= t7; h2[1] = p; }
        { float p = t4 * t5; p *= t6; p *= t7; p *= t8; h2[2] = p; }
        { float p = t5 * t6; p *= t7; p *= t8; p *= t9; h2[3] = p; }
        h3[0] = h2[0] * t1 * t7;
        h3[1] = h2[1] * t2 * t8;
        h3[2] = h2[2] * t3 * t9;
        h3[3] = h2[3] * t4 * t10;

        // rotating accumulator stages; slot = (ii - d) % 7 (static after unroll)
        acc[ii % 7] = make_float4(tm0, tm1, tm2, tm3);                    // d=0: t (dy=-3)
        { float4& a = acc[(ii + 6) % 7];                                  // d=1: h2 (dy=-2)
          a.x *= h2[0]; a.y *= h2[1]; a.z *= h2[2]; a.w *= h2[3]; }
        { float4& a = acc[(ii + 5) % 7];                                  // d=2: h2 (dy=-1)
          a.x *= h2[0]; a.y *= h2[1]; a.z *= h2[2]; a.w *= h2[3]; }
        { float4& a = acc[(ii + 4) % 7];                                  // d=3: h3 (dy=0)
          a.x *= h3[0]; a.y *= h3[1]; a.z *= h3[2]; a.w *= h3[3]; }
        { float4& a = acc[(ii + 3) % 7];                                  // d=4: h2 (dy=+1)
          a.x *= h2[0]; a.y *= h2[1]; a.z *= h2[2]; a.w *= h2[3]; }
        { float4& a = acc[(ii + 2) % 7];                                  // d=5: h2 (dy=+2)
          a.x *= h2[0]; a.y *= h2[1]; a.z *= h2[2]; a.w *= h2[3]; }

        if (emit) {                                                       // d=6: t (dy=+3)
            float4 a = acc[(ii + 1) % 7];
            a.x *= tm0; a.y *= tm1; a.z *= tm2; a.w *= tm3;

            float4 o;
            float m;
            m   = 1.f - a.x;   // a in [0,1] -> m in [0,1], no extra clip needed
            o.x = fminf(fmaxf(IWGT * xv.x + WGT * m, 0.f), 1.f);
            m   = 1.f - a.y;
            o.y = fminf(fmaxf(IWGT * xv.y + WGT * m, 0.f), 1.f);
            m   = 1.f - a.z;
            o.z = fminf(fmaxf(IWGT * xv.z + WGT * m, 0.f), 1.f);
            m   = 1.f - a.w;
            o.w = fminf(fmaxf(IWGT * xv.w + WGT * m, 0.f), 1.f);

            __stcs((float4*)(obase + y * Ww + c0), o);   // streaming store
        }

        M0 = M1; M1 = M2; M2 = Mnew;
    }
}

extern "C" void kernel_launch(void* const* d_in, const int* in_sizes, int n_in,
                              void* d_out, int out_size)
{
    (void)in_sizes; (void)n_in; (void)out_size;
    const float* x = (const float*)d_in[0];   // (16,1,512,512) fp32; d_in[1] = i (fixed 30)
    float* o = (float*)d_out;
    // 8192 warps = 16 imgs * 128 row-chunks * 4 column-quadrants = 1024 blocks
    // (~1.7 waves at 4 blocks/SM residency; second wave smooths CTA spread)
    morph_kernel<<<1024, 256>>>(x, o);
}